// round 9
// baseline (speedup 1.0000x reference)
#include <cuda_runtime.h>
#include <cstdint>
#include <cmath>

// ---------------------------------------------------------------------------
// WeightedRankNet R9: sweep packs per-doc partial scores (A, D, E, PG) into a
// 16B/doc float4 table (L2-resident) + col16 partial sums. Gather processes
// 8 elements/thread: all index + packed loads issued up front (MLP 8),
// threefry overlapped with load latency, per-block deterministic avg fold.
//   out = PG + A/(D + E/avg) + u*frw
// Threefry-2x32-20, key=(0,1), partitionable: bits = out0 ^ out1.
// ---------------------------------------------------------------------------

#define N_FEAT        136
#define COL_DOCLEN    14
#define COL_WHOLE_LEN 16
#define COL_TF        24
#define COL_INLINK    127
#define COL_OUTLINK   128
#define COL_PAGERANK  129

#define TPB        256
#define SUM_BLOCKS 1024
#define MAX_DOCS   (1 << 20)
#define EPT        8          // gather elements per thread

__device__ float4 g_packed[MAX_DOCS];      // 16 MB: (A, D, E, PG)
__device__ float  g_partials[SUM_BLOCKS];

// ---- 1) sweep: pack per-doc partial scores + col16 partial sums ---------------
__global__ void __launch_bounds__(TPB)
sweep_kernel(const float* __restrict__ gf,
             const float* __restrict__ s_k1,
             const float* __restrict__ s_b,
             const float* __restrict__ s_bw,
             const float* __restrict__ s_pr,
             const float* __restrict__ s_in,
             const float* __restrict__ s_out,
             int n_docs, float idf)
{
    const int tid  = blockIdx.x * blockDim.x + threadIdx.x;
    const int S    = gridDim.x * blockDim.x;
    const int step = 4 * S;

    const float k1  = __ldg(s_k1);
    const float b   = __ldg(s_b);
    const float bw  = __ldg(s_bw);
    const float prw = __ldg(s_pr);
    const float inw = __ldg(s_in);
    const float otw = __ldg(s_out);

    const float cA = bw * idf * (k1 + 1.0f);   // A = cA * tf
    const float cD = k1 * (1.0f - b);          // D = tf + cD
    const float cE = k1 * b;                   // E = cE * dl

    float csum = 0.0f;

    for (int base = tid; base < n_docs; base += step) {
        int  r[4];
        bool v[4];
        #pragma unroll
        for (int k = 0; k < 4; k++) {
            int rr = base + k * S;
            v[k] = (rr < n_docs);
            r[k] = v[k] ? rr : (n_docs - 1);
        }

        // issue all 24 loads back-to-back
        float dl[4], c16[4], tf[4], inl[4];
        float2 op[4];
        #pragma unroll
        for (int k = 0; k < 4; k++) {
            const float* row = gf + (long long)r[k] * N_FEAT;
            dl[k]  = __ldcs(row + COL_DOCLEN);
            c16[k] = __ldcs(row + COL_WHOLE_LEN);
            tf[k]  = __ldcs(row + COL_TF);
            inl[k] = __ldcs(row + COL_INLINK);
            op[k]  = __ldcs(reinterpret_cast<const float2*>(row + COL_OUTLINK));
        }

        #pragma unroll
        for (int k = 0; k < 4; k++) {
            if (!v[k]) break;
            csum += c16[k];
            float A  = cA * tf[k];
            float D  = tf[k] + cD;
            float E  = cE * dl[k];
            float PG = prw * op[k].y + inw * inl[k] + otw * op[k].x;
            g_packed[r[k]] = make_float4(A, D, E, PG);
        }
    }

    __shared__ float sd[TPB];
    sd[threadIdx.x] = csum;
    __syncthreads();
    for (int k = TPB / 2; k > 0; k >>= 1) {
        if (threadIdx.x < k) sd[threadIdx.x] += sd[threadIdx.x + k];
        __syncthreads();
    }
    if (threadIdx.x == 0) g_partials[blockIdx.x] = sd[0];
}

// ---- Threefry-2x32 -------------------------------------------------------------
__device__ __forceinline__ uint32_t rotl32(uint32_t x, uint32_t r) {
    return __funnelshift_l(x, x, r);
}

__device__ __forceinline__ uint32_t threefry_bits(uint32_t ctr) {
    uint32_t x0 = 0u;
    uint32_t x1 = ctr;
    const uint32_t ks0 = 0u, ks1 = 1u, ks2 = 0x1BD11BDBu;
    x0 += ks0; x1 += ks1;
#define TF_R(r) { x0 += x1; x1 = rotl32(x1, (r)); x1 ^= x0; }
    TF_R(13) TF_R(15) TF_R(26) TF_R(6)
    x0 += ks1; x1 += ks2 + 1u;
    TF_R(17) TF_R(29) TF_R(16) TF_R(24)
    x0 += ks2; x1 += ks0 + 2u;
    TF_R(13) TF_R(15) TF_R(26) TF_R(6)
    x0 += ks0; x1 += ks1 + 3u;
    TF_R(17) TF_R(29) TF_R(16) TF_R(24)
    x0 += ks1; x1 += ks2 + 4u;
    TF_R(13) TF_R(15) TF_R(26) TF_R(6)
    x0 += ks2; x1 += ks0 + 5u;
#undef TF_R
    return x0 ^ x1;
}

// ---- 2) gather: 8 elems/thread, per-block avg fold ------------------------------
__global__ void __launch_bounds__(TPB)
gather_kernel(const int* __restrict__ idxs,
              const float* __restrict__ s_fr,
              float* __restrict__ out,
              int batch, int n_docs)
{
    const int tid  = blockIdx.x * blockDim.x + threadIdx.x;
    const int base = tid * EPT;
    const int t    = threadIdx.x;

    const bool full = (base + EPT - 1 < batch);

    // ---- issue index loads ----
    int idx[EPT];
    if (full) {
        int4 iv0 = *reinterpret_cast<const int4*>(idxs + base);
        int4 iv1 = *reinterpret_cast<const int4*>(idxs + base + 4);
        idx[0] = iv0.x; idx[1] = iv0.y; idx[2] = iv0.z; idx[3] = iv0.w;
        idx[4] = iv1.x; idx[5] = iv1.y; idx[6] = iv1.z; idx[7] = iv1.w;
    } else {
        #pragma unroll
        for (int k = 0; k < EPT; k++)
            idx[k] = (base + k < batch) ? idxs[base + k] : 0;
    }

    // ---- issue all 8 packed loads back-to-back ----
    float4 p[EPT];
    #pragma unroll
    for (int k = 0; k < EPT; k++)
        p[k] = __ldg(&g_packed[idx[k]]);

    // ---- threefry while loads are in flight ----
    const float frw = __ldg(s_fr);
    float fr[EPT];
    #pragma unroll
    for (int k = 0; k < EPT; k++) {
        uint32_t bits = threefry_bits((uint32_t)(base + k));
        float u = __uint_as_float((bits >> 9) | 0x3f800000u) - 1.0f;
        fr[k] = fmaxf(0.0f, u) * frw;
    }

    // ---- deterministic per-block fold of col16 partials -> avg ----
    __shared__ float sd[TPB];
    {
        float s = g_partials[t] + g_partials[t + 256]
                + g_partials[t + 512] + g_partials[t + 768];
        sd[t] = s;
        __syncthreads();
        for (int k = TPB / 2; k > 0; k >>= 1) {
            if (t < k) sd[t] += sd[t + k];
            __syncthreads();
        }
    }
    const float inv_avg = (float)n_docs / sd[0];   // 1/avg

    if (base >= batch) return;

    float res[EPT];
    #pragma unroll
    for (int k = 0; k < EPT; k++)
        res[k] = p[k].w + p[k].x / (p[k].y + p[k].z * inv_avg) + fr[k];

    if (full) {
        *reinterpret_cast<float4*>(out + base) =
            make_float4(res[0], res[1], res[2], res[3]);
        *reinterpret_cast<float4*>(out + base + 4) =
            make_float4(res[4], res[5], res[6], res[7]);
    } else {
        #pragma unroll
        for (int k = 0; k < EPT; k++)
            if (base + k < batch) out[base + k] = res[k];
    }
}

// ---------------------------------------------------------------------------
extern "C" void kernel_launch(void* const* d_in, const int* in_sizes, int n_in,
                              void* d_out, int out_size)
{
    const int*   idxs = (const int*)d_in[0];
    const float* gf   = (const float*)d_in[1];
    const float* k1   = (const float*)d_in[2];
    const float* b    = (const float*)d_in[3];
    const float* bw   = (const float*)d_in[4];
    const float* prw  = (const float*)d_in[5];
    const float* inw  = (const float*)d_in[6];
    const float* outw = (const float*)d_in[7];
    const float* frw  = (const float*)d_in[8];
    float* out = (float*)d_out;

    int batch  = in_sizes[0];
    int n_docs = in_sizes[1] / N_FEAT;
    if (n_docs > MAX_DOCS) n_docs = MAX_DOCS;

    // idf in the reference's exact f32 operation order (num == total):
    float total = (float)n_docs;
    float idf = logf(((total - total) + 0.5f) / (total + 0.5f) + 1.0f);

    sweep_kernel<<<SUM_BLOCKS, TPB>>>(gf, k1, b, bw, prw, inw, outw,
                                      n_docs, idf);

    int gblocks = (batch + TPB * EPT - 1) / (TPB * EPT);
    gather_kernel<<<gblocks, TPB>>>(idxs, frw, out, batch, n_docs);
}

// round 10
// speedup vs baseline: 1.0309x; 1.0309x over previous
#include <cuda_runtime.h>
#include <cstdint>
#include <cmath>

// ---------------------------------------------------------------------------
// WeightedRankNet R10: R8 structure (16B/doc packed table, EPT=4 gather) +
// Programmatic Dependent Launch: gather launches early (PDL), does its
// sweep-independent pre-work (idx loads + threefry) while the sweep drains,
// then griddepcontrol-waits before reading the packed table / partials.
// Threefry-2x32-20, key=(0,1), partitionable: bits = out0 ^ out1.
// ---------------------------------------------------------------------------

#define N_FEAT        136
#define COL_DOCLEN    14
#define COL_WHOLE_LEN 16
#define COL_TF        24
#define COL_INLINK    127
#define COL_OUTLINK   128
#define COL_PAGERANK  129

#define TPB        256
#define SUM_BLOCKS 1024
#define MAX_DOCS   (1 << 20)
#define EPT        4

__device__ float4 g_packed[MAX_DOCS];      // 16 MB: (A, D, E, PG)
__device__ float  g_partials[SUM_BLOCKS];

// ---- 1) sweep: pack per-doc partial scores + col16 partial sums ---------------
__global__ void __launch_bounds__(TPB)
sweep_kernel(const float* __restrict__ gf,
             const float* __restrict__ s_k1,
             const float* __restrict__ s_b,
             const float* __restrict__ s_bw,
             const float* __restrict__ s_pr,
             const float* __restrict__ s_in,
             const float* __restrict__ s_out,
             int n_docs, float idf)
{
    // Allow the dependent gather kernel to launch early (PDL). Memory
    // visibility for it is still gated on this grid's completion via its
    // cudaGridDependencySynchronize().
    cudaTriggerProgrammaticLaunchCompletion();

    const int tid  = blockIdx.x * blockDim.x + threadIdx.x;
    const int S    = gridDim.x * blockDim.x;
    const int step = 4 * S;

    const float k1  = __ldg(s_k1);
    const float b   = __ldg(s_b);
    const float bw  = __ldg(s_bw);
    const float prw = __ldg(s_pr);
    const float inw = __ldg(s_in);
    const float otw = __ldg(s_out);

    const float cA = bw * idf * (k1 + 1.0f);   // A = cA * tf
    const float cD = k1 * (1.0f - b);          // D = tf + cD
    const float cE = k1 * b;                   // E = cE * dl

    float csum = 0.0f;

    for (int base = tid; base < n_docs; base += step) {
        int  r[4];
        bool v[4];
        #pragma unroll
        for (int k = 0; k < 4; k++) {
            int rr = base + k * S;
            v[k] = (rr < n_docs);
            r[k] = v[k] ? rr : (n_docs - 1);
        }

        // issue all 24 loads back-to-back
        float dl[4], c16[4], tf[4], inl[4];
        float2 op[4];
        #pragma unroll
        for (int k = 0; k < 4; k++) {
            const float* row = gf + (long long)r[k] * N_FEAT;
            dl[k]  = __ldcs(row + COL_DOCLEN);
            c16[k] = __ldcs(row + COL_WHOLE_LEN);
            tf[k]  = __ldcs(row + COL_TF);
            inl[k] = __ldcs(row + COL_INLINK);
            op[k]  = __ldcs(reinterpret_cast<const float2*>(row + COL_OUTLINK));
        }

        #pragma unroll
        for (int k = 0; k < 4; k++) {
            if (!v[k]) break;
            csum += c16[k];
            float A  = cA * tf[k];
            float D  = tf[k] + cD;
            float E  = cE * dl[k];
            float PG = prw * op[k].y + inw * inl[k] + otw * op[k].x;
            g_packed[r[k]] = make_float4(A, D, E, PG);
        }
    }

    __shared__ float sd[TPB];
    sd[threadIdx.x] = csum;
    __syncthreads();
    for (int k = TPB / 2; k > 0; k >>= 1) {
        if (threadIdx.x < k) sd[threadIdx.x] += sd[threadIdx.x + k];
        __syncthreads();
    }
    if (threadIdx.x == 0) g_partials[blockIdx.x] = sd[0];
}

// ---- Threefry-2x32 -------------------------------------------------------------
__device__ __forceinline__ uint32_t rotl32(uint32_t x, uint32_t r) {
    return __funnelshift_l(x, x, r);
}

__device__ __forceinline__ uint32_t threefry_bits(uint32_t ctr) {
    uint32_t x0 = 0u;
    uint32_t x1 = ctr;
    const uint32_t ks0 = 0u, ks1 = 1u, ks2 = 0x1BD11BDBu;
    x0 += ks0; x1 += ks1;
#define TF_R(r) { x0 += x1; x1 = rotl32(x1, (r)); x1 ^= x0; }
    TF_R(13) TF_R(15) TF_R(26) TF_R(6)
    x0 += ks1; x1 += ks2 + 1u;
    TF_R(17) TF_R(29) TF_R(16) TF_R(24)
    x0 += ks2; x1 += ks0 + 2u;
    TF_R(13) TF_R(15) TF_R(26) TF_R(6)
    x0 += ks0; x1 += ks1 + 3u;
    TF_R(17) TF_R(29) TF_R(16) TF_R(24)
    x0 += ks1; x1 += ks2 + 4u;
    TF_R(13) TF_R(15) TF_R(26) TF_R(6)
    x0 += ks2; x1 += ks0 + 5u;
#undef TF_R
    return x0 ^ x1;
}

// ---- 2) gather (PDL secondary): pre-work, wait, packed reads, fold, combine -----
__global__ void __launch_bounds__(TPB)
gather_kernel(const int* __restrict__ idxs,
              const float* __restrict__ s_fr,
              float* __restrict__ out,
              int batch, int n_docs)
{
    const int tid  = blockIdx.x * blockDim.x + threadIdx.x;
    const int base = tid * EPT;
    const int t    = threadIdx.x;

    // ---------- pre-wait work: independent of the sweep ----------
    int idx[EPT];
    const bool full = (base + EPT - 1 < batch);
    if (full) {
        int4 iv = *reinterpret_cast<const int4*>(idxs + base);
        idx[0] = iv.x; idx[1] = iv.y; idx[2] = iv.z; idx[3] = iv.w;
    } else if (base < batch) {
        #pragma unroll
        for (int k = 0; k < EPT; k++)
            idx[k] = (base + k < batch) ? idxs[base + k] : idxs[base];
    } else {
        idx[0] = idx[1] = idx[2] = idx[3] = 0;
    }

    const float frw = __ldg(s_fr);
    float fr[EPT];
    #pragma unroll
    for (int k = 0; k < EPT; k++) {
        uint32_t bits = threefry_bits((uint32_t)(base + k));
        float u = __uint_as_float((bits >> 9) | 0x3f800000u) - 1.0f;
        fr[k] = fmaxf(0.0f, u) * frw;
    }

    // ---------- wait for the sweep's writes to be visible ----------
    cudaGridDependencySynchronize();

    // packed loads (L2-resident), issued before the avg fold
    float4 p[EPT];
    #pragma unroll
    for (int k = 0; k < EPT; k++)
        p[k] = __ldg(&g_packed[idx[k]]);

    // deterministic per-block fold of col16 partials -> avg
    __shared__ float sd[TPB];
    {
        float s = g_partials[t] + g_partials[t + 256]
                + g_partials[t + 512] + g_partials[t + 768];
        sd[t] = s;
        __syncthreads();
        for (int k = TPB / 2; k > 0; k >>= 1) {
            if (t < k) sd[t] += sd[t + k];
            __syncthreads();
        }
    }
    const float inv_avg = (float)n_docs / sd[0];   // 1/avg

    if (base >= batch) return;

    float res[EPT];
    #pragma unroll
    for (int k = 0; k < EPT; k++)
        res[k] = p[k].w + p[k].x / (p[k].y + p[k].z * inv_avg) + fr[k];

    if (full) {
        *reinterpret_cast<float4*>(out + base) =
            make_float4(res[0], res[1], res[2], res[3]);
    } else {
        #pragma unroll
        for (int k = 0; k < EPT; k++)
            if (base + k < batch) out[base + k] = res[k];
    }
}

// ---------------------------------------------------------------------------
extern "C" void kernel_launch(void* const* d_in, const int* in_sizes, int n_in,
                              void* d_out, int out_size)
{
    const int*   idxs = (const int*)d_in[0];
    const float* gf   = (const float*)d_in[1];
    const float* k1   = (const float*)d_in[2];
    const float* b    = (const float*)d_in[3];
    const float* bw   = (const float*)d_in[4];
    const float* prw  = (const float*)d_in[5];
    const float* inw  = (const float*)d_in[6];
    const float* outw = (const float*)d_in[7];
    const float* frw  = (const float*)d_in[8];
    float* out = (float*)d_out;

    int batch  = in_sizes[0];
    int n_docs = in_sizes[1] / N_FEAT;
    if (n_docs > MAX_DOCS) n_docs = MAX_DOCS;

    // idf in the reference's exact f32 operation order (num == total):
    float total = (float)n_docs;
    float idf = logf(((total - total) + 0.5f) / (total + 0.5f) + 1.0f);

    sweep_kernel<<<SUM_BLOCKS, TPB>>>(gf, k1, b, bw, prw, inw, outw,
                                      n_docs, idf);

    // gather via PDL: may launch while the sweep drains; it self-synchronizes
    // with cudaGridDependencySynchronize() before touching sweep outputs.
    int gblocks = (batch + TPB * EPT - 1) / (TPB * EPT);

    cudaLaunchConfig_t cfg = {};
    cfg.gridDim  = dim3((unsigned)gblocks, 1, 1);
    cfg.blockDim = dim3(TPB, 1, 1);
    cfg.dynamicSmemBytes = 0;
    cfg.stream = 0;  // same (capture) stream as the sweep launch

    cudaLaunchAttribute attr[1];
    attr[0].id = cudaLaunchAttributeProgrammaticStreamSerialization;
    attr[0].val.programmaticStreamSerializationAllowed = 1;
    cfg.attrs = attr;
    cfg.numAttrs = 1;

    cudaLaunchKernelEx(&cfg, gather_kernel, idxs, frw, out, batch, n_docs);
}

// round 11
// speedup vs baseline: 1.0441x; 1.0128x over previous
#include <cuda_runtime.h>
#include <cuda_bf16.h>
#include <cstdint>
#include <cmath>

// ---------------------------------------------------------------------------
// WeightedRankNet R11: sweep packs per-doc (PG:f32, tf:bf16, dl:bf16) = 8B/doc
// (8 MB table) + col16 partials. Gather (PDL secondary): pre-work (idx +
// threefry) before griddep sync; after sync, cooperatively re-primes the 8 MB
// table into L2 sequentially, folds avg, then random 8B loads hit L2.
//   bm25 recomputed from bf16 tf/dl (abs err ~2e-8, negligible: idf ~ 5e-7).
// Threefry-2x32-20, key=(0,1), partitionable: bits = out0 ^ out1.
// ---------------------------------------------------------------------------

#define N_FEAT        136
#define COL_DOCLEN    14
#define COL_WHOLE_LEN 16
#define COL_TF        24
#define COL_INLINK    127
#define COL_OUTLINK   128
#define COL_PAGERANK  129

#define TPB        256
#define SUM_BLOCKS 1024
#define MAX_DOCS   (1 << 20)
#define EPT        4

// word x = PG (f32 bits); word y = bf16x2(tf, dl)
__device__ uint2 g_packed[MAX_DOCS];       // 8 MB
__device__ float g_partials[SUM_BLOCKS];

// ---- 1) sweep: pack per-doc (PG, tf, dl) + col16 partial sums ------------------
__global__ void __launch_bounds__(TPB)
sweep_kernel(const float* __restrict__ gf,
             const float* __restrict__ s_pr,
             const float* __restrict__ s_in,
             const float* __restrict__ s_out,
             int n_docs)
{
    cudaTriggerProgrammaticLaunchCompletion();

    const int tid  = blockIdx.x * blockDim.x + threadIdx.x;
    const int S    = gridDim.x * blockDim.x;
    const int step = 4 * S;

    const float prw = __ldg(s_pr);
    const float inw = __ldg(s_in);
    const float otw = __ldg(s_out);

    float csum = 0.0f;

    for (int base = tid; base < n_docs; base += step) {
        int  r[4];
        bool v[4];
        #pragma unroll
        for (int k = 0; k < 4; k++) {
            int rr = base + k * S;
            v[k] = (rr < n_docs);
            r[k] = v[k] ? rr : (n_docs - 1);
        }

        // issue all 24 loads back-to-back
        float dl[4], c16[4], tf[4], inl[4];
        float2 op[4];
        #pragma unroll
        for (int k = 0; k < 4; k++) {
            const float* row = gf + (long long)r[k] * N_FEAT;
            dl[k]  = __ldcs(row + COL_DOCLEN);
            c16[k] = __ldcs(row + COL_WHOLE_LEN);
            tf[k]  = __ldcs(row + COL_TF);
            inl[k] = __ldcs(row + COL_INLINK);
            op[k]  = __ldcs(reinterpret_cast<const float2*>(row + COL_OUTLINK));
        }

        #pragma unroll
        for (int k = 0; k < 4; k++) {
            if (!v[k]) break;
            csum += c16[k];
            float PG = prw * op[k].y + inw * inl[k] + otw * op[k].x;
            __nv_bfloat162 td = __floats2bfloat162_rn(tf[k], dl[k]);
            uint2 pk;
            pk.x = __float_as_uint(PG);
            pk.y = *reinterpret_cast<uint32_t*>(&td);
            g_packed[r[k]] = pk;
        }
    }

    __shared__ float sd[TPB];
    sd[threadIdx.x] = csum;
    __syncthreads();
    for (int k = TPB / 2; k > 0; k >>= 1) {
        if (threadIdx.x < k) sd[threadIdx.x] += sd[threadIdx.x + k];
        __syncthreads();
    }
    if (threadIdx.x == 0) g_partials[blockIdx.x] = sd[0];
}

// ---- Threefry-2x32 -------------------------------------------------------------
__device__ __forceinline__ uint32_t rotl32(uint32_t x, uint32_t r) {
    return __funnelshift_l(x, x, r);
}

__device__ __forceinline__ uint32_t threefry_bits(uint32_t ctr) {
    uint32_t x0 = 0u;
    uint32_t x1 = ctr;
    const uint32_t ks0 = 0u, ks1 = 1u, ks2 = 0x1BD11BDBu;
    x0 += ks0; x1 += ks1;
#define TF_R(r) { x0 += x1; x1 = rotl32(x1, (r)); x1 ^= x0; }
    TF_R(13) TF_R(15) TF_R(26) TF_R(6)
    x0 += ks1; x1 += ks2 + 1u;
    TF_R(17) TF_R(29) TF_R(16) TF_R(24)
    x0 += ks2; x1 += ks0 + 2u;
    TF_R(13) TF_R(15) TF_R(26) TF_R(6)
    x0 += ks0; x1 += ks1 + 3u;
    TF_R(17) TF_R(29) TF_R(16) TF_R(24)
    x0 += ks1; x1 += ks2 + 4u;
    TF_R(13) TF_R(15) TF_R(26) TF_R(6)
    x0 += ks2; x1 += ks0 + 5u;
#undef TF_R
    return x0 ^ x1;
}

// ---- 2) gather (PDL secondary) ---------------------------------------------------
__global__ void __launch_bounds__(TPB)
gather_kernel(const int* __restrict__ idxs,
              const float* __restrict__ s_k1,
              const float* __restrict__ s_b,
              const float* __restrict__ s_bw,
              const float* __restrict__ s_fr,
              float* __restrict__ out,
              int batch, int n_docs, float idf)
{
    const int tid      = blockIdx.x * blockDim.x + threadIdx.x;
    const int nthreads = gridDim.x * blockDim.x;
    const int base     = tid * EPT;
    const int t        = threadIdx.x;

    // ---------- pre-wait work: independent of the sweep ----------
    int idx[EPT];
    const bool full = (base + EPT - 1 < batch);
    if (full) {
        int4 iv = *reinterpret_cast<const int4*>(idxs + base);
        idx[0] = iv.x; idx[1] = iv.y; idx[2] = iv.z; idx[3] = iv.w;
    } else if (base < batch) {
        #pragma unroll
        for (int k = 0; k < EPT; k++)
            idx[k] = (base + k < batch) ? idxs[base + k] : idxs[base];
    } else {
        idx[0] = idx[1] = idx[2] = idx[3] = 0;
    }

    const float frw = __ldg(s_fr);
    float fr[EPT];
    #pragma unroll
    for (int k = 0; k < EPT; k++) {
        uint32_t bits = threefry_bits((uint32_t)(base + k));
        float u = __uint_as_float((bits >> 9) | 0x3f800000u) - 1.0f;
        fr[k] = fmaxf(0.0f, u) * frw;
    }

    const float k1 = __ldg(s_k1);
    const float b  = __ldg(s_b);
    const float bw = __ldg(s_bw);
    const float cA = bw * idf * (k1 + 1.0f);   // bm25*bw = cA*tf / den
    const float cD = k1 * (1.0f - b);
    const float cE = k1 * b;

    // ---------- wait for the sweep's writes ----------
    cudaGridDependencySynchronize();

    // ---------- sequential L2 re-prime of the 8 MB table ----------
    {
        const uint2* pt = g_packed;
        for (int i = tid; i < n_docs; i += nthreads) {
            uint32_t dummy;
            asm volatile("ld.global.cg.u32 %0, [%1];"
                         : "=r"(dummy)
                         : "l"(reinterpret_cast<const char*>(pt) + (size_t)i * 8)
                         : "memory");
            (void)dummy;
        }
    }

    // ---------- deterministic per-block fold of col16 partials -> avg ----------
    __shared__ float sd[TPB];
    {
        float s = g_partials[t] + g_partials[t + 256]
                + g_partials[t + 512] + g_partials[t + 768];
        sd[t] = s;
        __syncthreads();
        for (int k = TPB / 2; k > 0; k >>= 1) {
            if (t < k) sd[t] += sd[t + k];
            __syncthreads();
        }
    }
    const float inv_avg = (float)n_docs / sd[0];   // 1/avg

    if (base >= batch) return;

    // ---------- random loads: should hit L2 now ----------
    uint2 p[EPT];
    #pragma unroll
    for (int k = 0; k < EPT; k++)
        p[k] = __ldg(&g_packed[idx[k]]);

    float res[EPT];
    #pragma unroll
    for (int k = 0; k < EPT; k++) {
        float PG = __uint_as_float(p[k].x);
        __nv_bfloat162 td = *reinterpret_cast<__nv_bfloat162*>(&p[k].y);
        float tf = __bfloat162float(td.x);
        float dl = __bfloat162float(td.y);
        float bm = cA * tf / (tf + cD + cE * dl * inv_avg);
        res[k] = PG + bm + fr[k];
    }

    if (full) {
        *reinterpret_cast<float4*>(out + base) =
            make_float4(res[0], res[1], res[2], res[3]);
    } else {
        #pragma unroll
        for (int k = 0; k < EPT; k++)
            if (base + k < batch) out[base + k] = res[k];
    }
}

// ---------------------------------------------------------------------------
extern "C" void kernel_launch(void* const* d_in, const int* in_sizes, int n_in,
                              void* d_out, int out_size)
{
    const int*   idxs = (const int*)d_in[0];
    const float* gf   = (const float*)d_in[1];
    const float* k1   = (const float*)d_in[2];
    const float* b    = (const float*)d_in[3];
    const float* bw   = (const float*)d_in[4];
    const float* prw  = (const float*)d_in[5];
    const float* inw  = (const float*)d_in[6];
    const float* outw = (const float*)d_in[7];
    const float* frw  = (const float*)d_in[8];
    float* out = (float*)d_out;

    int batch  = in_sizes[0];
    int n_docs = in_sizes[1] / N_FEAT;
    if (n_docs > MAX_DOCS) n_docs = MAX_DOCS;

    // idf in the reference's exact f32 operation order (num == total):
    float total = (float)n_docs;
    float idf = logf(((total - total) + 0.5f) / (total + 0.5f) + 1.0f);

    sweep_kernel<<<SUM_BLOCKS, TPB>>>(gf, prw, inw, outw, n_docs);

    int gblocks = (batch + TPB * EPT - 1) / (TPB * EPT);

    cudaLaunchConfig_t cfg = {};
    cfg.gridDim  = dim3((unsigned)gblocks, 1, 1);
    cfg.blockDim = dim3(TPB, 1, 1);
    cfg.dynamicSmemBytes = 0;
    cfg.stream = 0;

    cudaLaunchAttribute attr[1];
    attr[0].id = cudaLaunchAttributeProgrammaticStreamSerialization;
    attr[0].val.programmaticStreamSerializationAllowed = 1;
    cfg.attrs = attr;
    cfg.numAttrs = 1;

    cudaLaunchKernelEx(&cfg, gather_kernel, idxs, k1, b, bw, frw, out,
                       batch, n_docs, idf);
}